// round 7
// baseline (speedup 1.0000x reference)
#include <cuda_runtime.h>

// LIF neuron group, T=1000 serial steps x 65536 neurons. Pure HBM stream
// (512 MB read + 256 MB write). History: depth knob (reg-resident rotating
// buffers) took DRAM 63.8 -> 83.0% but saturated at quad/quint (R5==R6).
// R7 hypothesis: all blocks run identical code in lockstep -> chip-wide
// load-burst / compute-drain phasing leaves DRAM idle 17% of cycles.
// Fix: scalar float lanes, 2048 one-warp blocks (~14 warps/SM, 0.5%
// imbalance), 2x independent issue streams that drift out of phase, finer
// request granularity. Keep deep rotation: 6 buffers, load 5 blocks ahead
// (~10.5 MB chip-wide in flight), regs ~120.

#define NUM_NEURONS 65536
#define T_STEPS     1000
#define NLANE       NUM_NEURONS           // 65536 scalar lanes
#define THREADS     32                    // 1 warp per block
#define BLOCKS      (NLANE / THREADS)     // 2048 blocks -> 14 vs 13 per SM
#define STAGES      8                     // timesteps per pipeline block (125 blocks)

__device__ __forceinline__ float lif_step(const float i1, const float n1,
                                          float& V, float& th)
{
    const float decay = 0.05f, eta = 0.1f, nstd = 0.1f;
    const float thmin = 0.5f, thmax = 2.0f;
    float ie = fmaf(nstd, n1, i1);
    float v  = fmaf(decay, ie - V, V);
    bool  sp = (v >= th);
    float s  = sp ? 1.0f : 0.0f;
    V  = sp ? 0.0f : v;
    th = fminf(fmaxf(fmaf(eta, s, th), thmin), thmax);
    return s;
}

__global__ __launch_bounds__(THREADS, 14)
void lif_kernel(const float* __restrict__ icur,
                const float* __restrict__ nz,
                float* __restrict__ out)
{
    const int idx = blockIdx.x * THREADS + threadIdx.x;   // 0 .. NLANE-1

    const float* ip = icur + idx;
    const float* np = nz   + idx;
    float*       op = out  + idx;

    float V  = 0.0f;
    float th = 1.0f;

    float AI[STAGES], AN[STAGES];
    float BI[STAGES], BN[STAGES];
    float CI[STAGES], CN[STAGES];
    float DI[STAGES], DN[STAGES];
    float EI[STAGES], EN[STAGES];
    float FI[STAGES], FN[STAGES];

    // blk b covers timesteps [b*STAGES, (b+1)*STAGES)
#define LOAD_BLK(I_, N_, b)                                           \
    _Pragma("unroll")                                                 \
    for (int j = 0; j < STAGES; j++) {                                \
        I_[j] = __ldcs(ip + (size_t)((b) * STAGES + j) * NLANE);      \
        N_[j] = __ldcs(np + (size_t)((b) * STAGES + j) * NLANE);      \
    }

#define COMP_BLK(I_, N_, b)                                           \
    _Pragma("unroll")                                                 \
    for (int j = 0; j < STAGES; j++) {                                \
        float s = lif_step(I_[j], N_[j], V, th);                      \
        __stcs(op + (size_t)((b) * STAGES + j) * NLANE, s);           \
    }

    // 125 blocks of 8. Six rotating buffers: loads run 5 blocks ahead.
    LOAD_BLK(AI, AN, 0)
    LOAD_BLK(BI, BN, 1)
    LOAD_BLK(CI, CN, 2)
    LOAD_BLK(DI, DN, 3)
    LOAD_BLK(EI, EN, 4)

    for (int p = 0; p < 20; p++) {
        const int b = 6 * p;                                 // 0,6,...,114
        LOAD_BLK(FI, FN, b + 5)    COMP_BLK(AI, AN, b)       // load <= 119
        LOAD_BLK(AI, AN, b + 6)    COMP_BLK(BI, BN, b + 1)   // load <= 120
        LOAD_BLK(BI, BN, b + 7)    COMP_BLK(CI, CN, b + 2)   // load <= 121
        LOAD_BLK(CI, CN, b + 8)    COMP_BLK(DI, DN, b + 3)   // load <= 122
        LOAD_BLK(DI, DN, b + 9)    COMP_BLK(EI, EN, b + 4)   // load <= 123
        LOAD_BLK(EI, EN, b + 10)   COMP_BLK(FI, FN, b + 5)   // load <= 124
    }
    // computed 0..119; A=120, B=121, C=122, D=123, E=124
    COMP_BLK(AI, AN, 120)
    COMP_BLK(BI, BN, 121)
    COMP_BLK(CI, CN, 122)
    COMP_BLK(DI, DN, 123)
    COMP_BLK(EI, EN, 124)

#undef LOAD_BLK
#undef COMP_BLK
}

extern "C" void kernel_launch(void* const* d_in, const int* in_sizes, int n_in,
                              void* d_out, int out_size)
{
    const float* icur = (const float*)d_in[0];   // input_current (T, N) f32
    const float* nz   = (const float*)d_in[1];   // noise         (T, N) f32
    float*       out  = (float*)d_out;           // spikes        (T, N) f32

    lif_kernel<<<BLOCKS, THREADS>>>(icur, nz, out);
}

// round 8
// speedup vs baseline: 1.0467x; 1.0467x over previous
#include <cuda_runtime.h>

// LIF neuron group, T=1000 serial steps x 65536 neurons. Pure HBM/LTS stream
// (512 MB read + 256 MB write). Validated across R2..R7: DRAM% is a
// saturating function of chip-wide in-flight load bytes; warp count and
// phasing are NOT the binder (R7 falsified). Achieved 6.58 TB/s is ~95% of
// the ~6300 B/cyc LTS fabric cap at memory-bound clocks.
// R8: champion layout (float2 lanes, 1024 one-warp blocks, 7-vs-6 per SM)
// with STAGES=5 x 8 rotating buffers (load 7 ahead): in-flight 560 B/thread
// (~18.4 MB) and 10-LDG bursts instead of 16 -> smoother request supply at
// equal register budget (~185).

#define NUM_NEURONS 65536
#define T_STEPS     1000
#define NVEC        (NUM_NEURONS / 2)     // 32768 float2 lanes
#define THREADS     32                    // 1 warp per block
#define BLOCKS      (NVEC / THREADS)      // 1024 blocks
#define STAGES      5                     // timesteps per pipeline block (200 blocks)

__device__ __forceinline__ float2 lif_step(const float2 i2, const float2 n2,
                                           float2& V, float2& th)
{
    const float decay = 0.05f, eta = 0.1f, nstd = 0.1f;
    const float thmin = 0.5f, thmax = 2.0f;
    float2 s;
#define LIF_C(c)                                                     \
    {                                                                \
        float ie = fmaf(nstd, n2.c, i2.c);                           \
        float v  = fmaf(decay, ie - V.c, V.c);                       \
        bool  sp = (v >= th.c);                                      \
        s.c  = sp ? 1.0f : 0.0f;                                     \
        V.c  = sp ? 0.0f : v;                                        \
        th.c = fminf(fmaxf(fmaf(eta, s.c, th.c), thmin), thmax);     \
    }
    LIF_C(x) LIF_C(y)
#undef LIF_C
    return s;
}

__global__ __launch_bounds__(THREADS, 7)
void lif_kernel(const float2* __restrict__ icur,
                const float2* __restrict__ nz,
                float2* __restrict__ out)
{
    const int idx = blockIdx.x * THREADS + threadIdx.x;   // 0 .. NVEC-1

    const float2* ip = icur + idx;
    const float2* np = nz   + idx;
    float2*       op = out  + idx;

    float2 V  = make_float2(0.0f, 0.0f);
    float2 th = make_float2(1.0f, 1.0f);

    float2 AI[STAGES], AN[STAGES];
    float2 BI[STAGES], BN[STAGES];
    float2 CI[STAGES], CN[STAGES];
    float2 DI[STAGES], DN[STAGES];
    float2 EI[STAGES], EN[STAGES];
    float2 FI[STAGES], FN[STAGES];
    float2 GI[STAGES], GN[STAGES];
    float2 HI[STAGES], HN[STAGES];

    // blk b covers timesteps [b*STAGES, (b+1)*STAGES)
#define LOAD_BLK(I_, N_, b)                                           \
    _Pragma("unroll")                                                 \
    for (int j = 0; j < STAGES; j++) {                                \
        I_[j] = __ldcs(ip + (size_t)((b) * STAGES + j) * NVEC);       \
        N_[j] = __ldcs(np + (size_t)((b) * STAGES + j) * NVEC);      \
    }

#define COMP_BLK(I_, N_, b)                                           \
    _Pragma("unroll")                                                 \
    for (int j = 0; j < STAGES; j++) {                                \
        float2 s = lif_step(I_[j], N_[j], V, th);                     \
        __stcs(op + (size_t)((b) * STAGES + j) * NVEC, s);            \
    }

    // 200 blocks of 5. Eight rotating buffers: loads run 7 blocks ahead.
    LOAD_BLK(AI, AN, 0)
    LOAD_BLK(BI, BN, 1)
    LOAD_BLK(CI, CN, 2)
    LOAD_BLK(DI, DN, 3)
    LOAD_BLK(EI, EN, 4)
    LOAD_BLK(FI, FN, 5)
    LOAD_BLK(GI, GN, 6)

    for (int p = 0; p < 24; p++) {
        const int b = 8 * p;                                 // 0,8,...,184
        LOAD_BLK(HI, HN, b + 7)    COMP_BLK(AI, AN, b)       // load <= 191
        LOAD_BLK(AI, AN, b + 8)    COMP_BLK(BI, BN, b + 1)   // load <= 192
        LOAD_BLK(BI, BN, b + 9)    COMP_BLK(CI, CN, b + 2)   // load <= 193
        LOAD_BLK(CI, CN, b + 10)   COMP_BLK(DI, DN, b + 3)   // load <= 194
        LOAD_BLK(DI, DN, b + 11)   COMP_BLK(EI, EN, b + 4)   // load <= 195
        LOAD_BLK(EI, EN, b + 12)   COMP_BLK(FI, FN, b + 5)   // load <= 196
        LOAD_BLK(FI, FN, b + 13)   COMP_BLK(GI, GN, b + 6)   // load <= 197
        LOAD_BLK(GI, GN, b + 14)   COMP_BLK(HI, HN, b + 7)   // load <= 198
    }
    // computed 0..191; A=192, B=193, C=194, D=195, E=196, F=197, G=198
    LOAD_BLK(HI, HN, 199)   COMP_BLK(AI, AN, 192)
    COMP_BLK(BI, BN, 193)
    COMP_BLK(CI, CN, 194)
    COMP_BLK(DI, DN, 195)
    COMP_BLK(EI, EN, 196)
    COMP_BLK(FI, FN, 197)
    COMP_BLK(GI, GN, 198)
    COMP_BLK(HI, HN, 199)

#undef LOAD_BLK
#undef COMP_BLK
}

extern "C" void kernel_launch(void* const* d_in, const int* in_sizes, int n_in,
                              void* d_out, int out_size)
{
    const float2* icur = (const float2*)d_in[0];   // input_current (T, N) f32
    const float2* nz   = (const float2*)d_in[1];   // noise         (T, N) f32
    float2*       out  = (float2*)d_out;           // spikes        (T, N) f32

    lif_kernel<<<BLOCKS, THREADS>>>(icur, nz, out);
}